// round 11
// baseline (speedup 1.0000x reference)
#include <cuda_runtime.h>
#include <cuda_fp16.h>
#include <math.h>
#include <stdint.h>

#define TT 2048
#define HH 2048
#define EE 8
#define II 4096
#define NSTAGE 4
#define STGB 49152          // bytes/stage: A 32 KB (256 rows) + B 16 KB (128 rows)
#define BOFF 32768          // B region byte offset within stage

// ---- scratch (device globals; no allocations allowed) ----
__device__ int    g_count[EE];
__device__ int    g_tok[EE * TT];
__device__ float  g_wt[EE * TT];
__device__ __half g_xh[TT * HH];             // fp16 x (8 MB)
__device__ __half g_hh[(size_t)EE * TT * II];// fp16 h (134 MB)
__device__ __half g_w13h[(size_t)EE * 2 * II * HH]; // fp16 w13 (268 MB)
__device__ __half g_w2h[(size_t)EE * HH * II];      // fp16 w2 (134 MB)

// ---------------------------------------------------------------------------
__global__ void zero_counts_k() {
    if (threadIdx.x < EE) g_count[threadIdx.x] = 0;
}

// One-time (per launch) weight conversion fp32 -> fp16 (pure DRAM-bound).
__global__ __launch_bounds__(256) void cvt_w_k(const float* __restrict__ w13,
                                               const float* __restrict__ w2) {
    const size_t n13 = (size_t)EE * 2 * II * HH / 4;  // float4 count
    const size_t n2  = (size_t)EE * HH * II / 4;
    const size_t stride = (size_t)gridDim.x * blockDim.x;
    for (size_t i = (size_t)blockIdx.x * blockDim.x + threadIdx.x;
         i < n13 + n2; i += stride) {
        if (i < n13) {
            float4 v = ((const float4*)w13)[i];
            ((__half2*)g_w13h)[2 * i]     = __floats2half2_rn(v.x, v.y);
            ((__half2*)g_w13h)[2 * i + 1] = __floats2half2_rn(v.z, v.w);
        } else {
            size_t j = i - n13;
            float4 v = ((const float4*)w2)[j];
            ((__half2*)g_w2h)[2 * j]     = __floats2half2_rn(v.x, v.y);
            ((__half2*)g_w2h)[2 * j + 1] = __floats2half2_rn(v.z, v.w);
        }
    }
}

// Router: exact fp32 logits/topk; also writes fp16 x row.
__global__ __launch_bounds__(256) void router_k(const float* __restrict__ x,
                                                const float* __restrict__ gw) {
    const int t = blockIdx.x;
    const int tid = threadIdx.x, w = tid >> 5, lane = tid & 31;
    __shared__ float logits[EE];
    const float* xr = x + (size_t)t * HH;
    const float* gr = gw + (size_t)w * HH;
    float s = 0.f;
    for (int k = lane; k < HH; k += 32) s = fmaf(xr[k], gr[k], s);
#pragma unroll
    for (int o = 16; o; o >>= 1) s += __shfl_xor_sync(0xffffffffu, s, o);
    if (lane == 0) logits[w] = s;
    __half* xo = g_xh + (size_t)t * HH;
    for (int k = tid; k < HH; k += 256) xo[k] = __float2half_rn(xr[k]);
    __syncthreads();
    if (tid == 0) {
        float m = logits[0];
#pragma unroll
        for (int i = 1; i < EE; ++i) m = fmaxf(m, logits[i]);
        float p[EE];
#pragma unroll
        for (int i = 0; i < EE; ++i) p[i] = expf(logits[i] - m);
        int a = 0;
#pragma unroll
        for (int i = 1; i < EE; ++i) if (p[i] > p[a]) a = i;
        int b = (a == 0) ? 1 : 0;
#pragma unroll
        for (int i = 0; i < EE; ++i) if (i != a && p[i] > p[b]) b = i;
        const float r = 1.f / (p[a] + p[b]);
        int pa = atomicAdd(&g_count[a], 1);
        g_tok[a * TT + pa] = t; g_wt[a * TT + pa] = p[a] * r;
        int pb = atomicAdd(&g_count[b], 1);
        g_tok[b * TT + pb] = t; g_wt[b * TT + pb] = p[b] * r;
    }
}

// ---------------------------------------------------------------------------
__device__ __forceinline__ uint32_t swz(uint32_t o) { return o ^ ((o >> 3) & 0x70); }

__device__ __forceinline__ void mma16(float* c, const uint32_t* a,
                                      uint32_t b0, uint32_t b1) {
    asm volatile(
        "mma.sync.aligned.m16n8k16.row.col.f32.f16.f16.f32 "
        "{%0,%1,%2,%3},{%4,%5,%6,%7},{%8,%9},{%0,%1,%2,%3};"
        : "+f"(c[0]), "+f"(c[1]), "+f"(c[2]), "+f"(c[3])
        : "r"(a[0]), "r"(a[1]), "r"(a[2]), "r"(a[3]), "r"(b0), "r"(b1));
}
#define LDM4(r, addr)                                                        \
    asm volatile("ldmatrix.sync.aligned.m8n8.x4.shared.b16 {%0,%1,%2,%3},[%4];" \
                 : "=r"((r)[0]), "=r"((r)[1]), "=r"((r)[2]), "=r"((r)[3])    \
                 : "r"(addr))
#define CP16(so, gp) \
    asm volatile("cp.async.cg.shared.global [%0], [%1], 16;" :: "r"(so), "l"(gp))
#define CP_COMMIT() asm volatile("cp.async.commit_group;" ::: "memory")
#define CP_WAIT2()  asm volatile("cp.async.wait_group 2;" ::: "memory")
#define CP_WAIT0()  asm volatile("cp.async.wait_group 0;" ::: "memory")

// ---------------------------------------------------------------------------
// GEMM1: block 256(M) x 64(N of gate AND up), BK=64 halves, 4-stage cp.async,
// fp16 smem SW128 + ldmatrix. 512 threads; warps 8(M) x 2(N);
// warp tile 32x32 dual accumulator (gate+up).
__global__ __launch_bounds__(512, 1) void gemm1_fp16() {
    extern __shared__ char smraw[];
    char* smal = (char*)(((uintptr_t)smraw + 1023) & ~(uintptr_t)1023);
    const int e = blockIdx.z;
    const int cnt = g_count[e];
    const int m0 = blockIdx.y * 256;
    if (m0 >= cnt) return;
    const int n0 = blockIdx.x * 64;

    const int tid = threadIdx.x;
    const uint32_t sbase = (uint32_t)__cvta_generic_to_shared(smal);

    // staging: per thread 4 A chunks (256 rows) + 2 B chunks (128 rows), 16 B each
    const __half* aG[4]; uint32_t aS[4];
    const __half* bG[2]; uint32_t bS[2];
#pragma unroll
    for (int i = 0; i < 4; ++i) {
        int c = tid + i * 512;
        int r = c >> 3, kg = c & 7;
        int slot = m0 + r; if (slot > cnt - 1) slot = cnt - 1;
        aG[i] = g_xh + (size_t)g_tok[e * TT + slot] * HH + kg * 8;
        aS[i] = swz(r * 128 + kg * 16);
    }
#pragma unroll
    for (int i = 0; i < 2; ++i) {
        int c = tid + i * 512;
        int r = c >> 3, kg = c & 7;
        size_t row = (r < 64) ? (size_t)(n0 + r) : (size_t)(II + n0 + (r - 64));
        bG[i] = g_w13h + (size_t)e * 2 * II * HH + row * HH + kg * 8;
        bS[i] = BOFF + swz(r * 128 + kg * 16);
    }

#define ISSUE1(s, k0)                                                   \
    {                                                                   \
        const uint32_t sb = sbase + (s) * STGB;                         \
        _Pragma("unroll") for (int i = 0; i < 4; ++i)                   \
            CP16(sb + aS[i], aG[i] + (k0));                             \
        _Pragma("unroll") for (int i = 0; i < 2; ++i)                   \
            CP16(sb + bS[i], bG[i] + (k0));                             \
    }

    const int lane = tid & 31, wid = tid >> 5;
    const int grp = lane >> 2, tig = lane & 3;
    const int wm = (wid & 7) * 32, wn = (wid >> 3) * 32;

    // ldmatrix address precompute (add-then-xor; adds never carry across row bits)
    const uint32_t arel = (uint32_t)(wm + (lane & 15)) * 128 + ((lane >> 4) & 1) * 16;
    const uint32_t amask = (arel >> 3) & 0x70;
    const uint32_t brel = (uint32_t)(wn + ((lane >> 4) & 1) * 8 + (lane & 7)) * 128
                        + ((lane >> 3) & 1) * 16;
    const uint32_t bmask = (brel >> 3) & 0x70;

    float cgr[2][4][4] = {};
    float cur[2][4][4] = {};

    ISSUE1(0, 0); CP_COMMIT();
    ISSUE1(1, 64); CP_COMMIT();
    ISSUE1(2, 128); CP_COMMIT();

    const int NT = HH / 64;  // 32
    for (int k = 0; k < NT; ++k) {
        CP_WAIT2();
        __syncthreads();
        const uint32_t su = sbase + (k & 3) * STGB;
#pragma unroll
        for (int kc4 = 0; kc4 < 4; ++kc4) {
            const uint32_t kcb = kc4 * 32;
            uint32_t af[2][4];
#pragma unroll
            for (int i = 0; i < 2; ++i)
                LDM4(af[i], su + (((arel + kcb + 2048 * i) ^ amask)));
#pragma unroll
            for (int jj = 0; jj < 2; ++jj) {
                uint32_t bg[4], bu[4];
                const uint32_t bb = brel + kcb + 2048 * jj;
                LDM4(bg, su + BOFF + ((bb) ^ bmask));
                LDM4(bu, su + BOFF + ((bb + 8192) ^ bmask));
#pragma unroll
                for (int i = 0; i < 2; ++i) {
                    mma16(cgr[i][2 * jj],     af[i], bg[0], bg[1]);
                    mma16(cgr[i][2 * jj + 1], af[i], bg[2], bg[3]);
                    mma16(cur[i][2 * jj],     af[i], bu[0], bu[1]);
                    mma16(cur[i][2 * jj + 1], af[i], bu[2], bu[3]);
                }
            }
        }
        const int kn = k + 3;
        if (kn < NT) ISSUE1(kn & 3, kn * 64);
        CP_COMMIT();
    }
    CP_WAIT0();

    // epilogue: swiglu * wt -> g_hh (fp16)
#pragma unroll
    for (int i = 0; i < 2; ++i) {
#pragma unroll
        for (int half = 0; half < 2; ++half) {
            const int slot = m0 + wm + 16 * i + grp + 8 * half;
            if (slot < cnt) {
                const float wt = g_wt[e * TT + slot];
                __half* hrow = g_hh + ((size_t)e * TT + slot) * II + n0 + wn;
#pragma unroll
                for (int j = 0; j < 4; ++j) {
                    const float g0 = cgr[i][j][2 * half], g1 = cgr[i][j][2 * half + 1];
                    const float u0 = cur[i][j][2 * half], u1 = cur[i][j][2 * half + 1];
                    const float v0 = wt * (g0 / (1.f + __expf(-g0))) * u0;
                    const float v1 = wt * (g1 / (1.f + __expf(-g1))) * u1;
                    *(__half2*)&hrow[8 * j + 2 * tig] = __floats2half2_rn(v0, v1);
                }
            }
        }
    }
#undef ISSUE1
}

// ---------------------------------------------------------------------------
// GEMM2: block 256(M) x 128(N), BK=64 halves, 4-stage, fp16 + ldmatrix.
// 512 threads; warps 8(M) x 2(N); warp tile 32x64. Scatter atomicAdd epilogue.
__global__ __launch_bounds__(512, 1) void gemm2_fp16(float* __restrict__ out) {
    extern __shared__ char smraw[];
    char* smal = (char*)(((uintptr_t)smraw + 1023) & ~(uintptr_t)1023);
    const int e = blockIdx.z;
    const int cnt = g_count[e];
    const int m0 = blockIdx.y * 256;
    if (m0 >= cnt) return;
    const int n0 = blockIdx.x * 128;

    const int tid = threadIdx.x;
    const uint32_t sbase = (uint32_t)__cvta_generic_to_shared(smal);

    const __half* aG[4]; uint32_t aS[4];
    const __half* bG[2]; uint32_t bS[2];
#pragma unroll
    for (int i = 0; i < 4; ++i) {
        int c = tid + i * 512;
        int r = c >> 3, kg = c & 7;
        int slot = m0 + r; if (slot > cnt - 1) slot = cnt - 1;
        aG[i] = g_hh + ((size_t)e * TT + slot) * II + kg * 8;
        aS[i] = swz(r * 128 + kg * 16);
    }
#pragma unroll
    for (int i = 0; i < 2; ++i) {
        int c = tid + i * 512;
        int r = c >> 3, kg = c & 7;
        bG[i] = g_w2h + (size_t)e * HH * II + (size_t)(n0 + r) * II + kg * 8;
        bS[i] = BOFF + swz(r * 128 + kg * 16);
    }

#define ISSUE2(s, k0)                                                   \
    {                                                                   \
        const uint32_t sb = sbase + (s) * STGB;                         \
        _Pragma("unroll") for (int i = 0; i < 4; ++i)                   \
            CP16(sb + aS[i], aG[i] + (k0));                             \
        _Pragma("unroll") for (int i = 0; i < 2; ++i)                   \
            CP16(sb + bS[i], bG[i] + (k0));                             \
    }

    const int lane = tid & 31, wid = tid >> 5;
    const int grp = lane >> 2, tig = lane & 3;
    const int wm = (wid & 7) * 32, wn = (wid >> 3) * 64;

    const uint32_t arel = (uint32_t)(wm + (lane & 15)) * 128 + ((lane >> 4) & 1) * 16;
    const uint32_t amask = (arel >> 3) & 0x70;
    const uint32_t brel = (uint32_t)(wn + ((lane >> 4) & 1) * 8 + (lane & 7)) * 128
                        + ((lane >> 3) & 1) * 16;
    const uint32_t bmask = (brel >> 3) & 0x70;

    float cc[2][8][4] = {};

    ISSUE2(0, 0); CP_COMMIT();
    ISSUE2(1, 64); CP_COMMIT();
    ISSUE2(2, 128); CP_COMMIT();

    const int NT = II / 64;  // 64
    for (int k = 0; k < NT; ++k) {
        CP_WAIT2();
        __syncthreads();
        const uint32_t su = sbase + (k & 3) * STGB;
#pragma unroll
        for (int kc4 = 0; kc4 < 4; ++kc4) {
            const uint32_t kcb = kc4 * 32;
            uint32_t af[2][4];
#pragma unroll
            for (int i = 0; i < 2; ++i)
                LDM4(af[i], su + (((arel + kcb + 2048 * i) ^ amask)));
#pragma unroll
            for (int jj = 0; jj < 4; ++jj) {
                uint32_t bb4[4];
                LDM4(bb4, su + BOFF + (((brel + kcb + 2048 * jj) ^ bmask)));
#pragma unroll
                for (int i = 0; i < 2; ++i) {
                    mma16(cc[i][2 * jj],     af[i], bb4[0], bb4[1]);
                    mma16(cc[i][2 * jj + 1], af[i], bb4[2], bb4[3]);
                }
            }
        }
        const int kn = k + 3;
        if (kn < NT) ISSUE2(kn & 3, kn * 64);
        CP_COMMIT();
    }
    CP_WAIT0();

#pragma unroll
    for (int i = 0; i < 2; ++i) {
#pragma unroll
        for (int half = 0; half < 2; ++half) {
            const int slot = m0 + wm + 16 * i + grp + 8 * half;
            if (slot < cnt) {
                const int tok = g_tok[e * TT + slot];
                float* orow = out + (size_t)tok * HH + n0 + wn;
#pragma unroll
                for (int j = 0; j < 8; ++j) {
                    atomicAdd(&orow[8 * j + 2 * tig], cc[i][j][2 * half]);
                    atomicAdd(&orow[8 * j + 2 * tig + 1], cc[i][j][2 * half + 1]);
                }
            }
        }
    }
#undef ISSUE2
}

// ---------------------------------------------------------------------------
extern "C" void kernel_launch(void* const* d_in, const int* in_sizes, int n_in,
                              void* d_out, int out_size) {
    const float* x   = (const float*)d_in[0];  // [T, H]
    const float* gw  = (const float*)d_in[1];  // [E, H]
    const float* w13 = (const float*)d_in[2];  // [E, 2I, H]
    const float* w2  = (const float*)d_in[3];  // [E, H, I]
    float* out = (float*)d_out;                // [T, H] fp32

    const int dsm = NSTAGE * STGB + 1024;  // 197632 B
    cudaFuncSetAttribute(gemm1_fp16, cudaFuncAttributeMaxDynamicSharedMemorySize, dsm);
    cudaFuncSetAttribute(gemm2_fp16, cudaFuncAttributeMaxDynamicSharedMemorySize, dsm);

    cudaMemsetAsync(out, 0, (size_t)TT * HH * sizeof(float));
    zero_counts_k<<<1, 32>>>();
    cvt_w_k<<<4096, 256>>>(w13, w2);
    router_k<<<TT, 256>>>(x, gw);
    gemm1_fp16<<<dim3(II / 64, TT / 256, EE), 512, dsm>>>();
    gemm2_fp16<<<dim3(HH / 128, TT / 256, EE), 512, dsm>>>(out);
}

// round 13
// speedup vs baseline: 1.2588x; 1.2588x over previous
#include <cuda_runtime.h>
#include <cuda_fp16.h>
#include <math.h>
#include <stdint.h>

#define TT 2048
#define HH 2048
#define EE 8
#define II 4096
#define NSTAGE 3
#define STGB 32768          // bytes/stage: A 16 KB + B 16 KB (128 rows x 128 B each)
#define BOFF 16384          // B region byte offset within stage
#define CVTB 4096           // cvt blocks in fused prep kernel

// ---- scratch (device globals; no allocations allowed) ----
__device__ int    g_count[EE];
__device__ int    g_tok[EE * TT];
__device__ float  g_wt[EE * TT];
__device__ __half g_xh[TT * HH];             // fp16 x (8 MB)
__device__ __half g_hh[(size_t)EE * TT * II];// fp16 h (134 MB)
__device__ __half g_w13h[(size_t)EE * 2 * II * HH]; // fp16 w13 (268 MB)
__device__ __half g_w2h[(size_t)EE * HH * II];      // fp16 w2 (134 MB)

// ---------------------------------------------------------------------------
__global__ void zero_counts_k() {
    if (threadIdx.x < EE) g_count[threadIdx.x] = 0;
}

// Fused prep: blocks [0, CVTB) convert weights fp32->fp16 (DRAM-bound);
// blocks [CVTB, CVTB+TT) run the router (latency-bound, hides under cvt).
__global__ __launch_bounds__(256) void prep_k(const float* __restrict__ x,
                                              const float* __restrict__ gw,
                                              const float* __restrict__ w13,
                                              const float* __restrict__ w2) {
    if (blockIdx.x < CVTB) {
        // ---- weight conversion ----
        const size_t n13 = (size_t)EE * 2 * II * HH / 4;  // float4 count
        const size_t n2  = (size_t)EE * HH * II / 4;
        const size_t stride = (size_t)CVTB * 256;
        for (size_t i = (size_t)blockIdx.x * 256 + threadIdx.x;
             i < n13 + n2; i += stride) {
            if (i < n13) {
                float4 v = ((const float4*)w13)[i];
                ((__half2*)g_w13h)[2 * i]     = __floats2half2_rn(v.x, v.y);
                ((__half2*)g_w13h)[2 * i + 1] = __floats2half2_rn(v.z, v.w);
            } else {
                size_t j = i - n13;
                float4 v = ((const float4*)w2)[j];
                ((__half2*)g_w2h)[2 * j]     = __floats2half2_rn(v.x, v.y);
                ((__half2*)g_w2h)[2 * j + 1] = __floats2half2_rn(v.z, v.w);
            }
        }
        return;
    }
    // ---- router: exact fp32 logits/topk; also writes fp16 x row ----
    const int t = blockIdx.x - CVTB;
    const int tid = threadIdx.x, w = tid >> 5, lane = tid & 31;
    __shared__ float logits[EE];
    const float* xr = x + (size_t)t * HH;
    const float* gr = gw + (size_t)w * HH;
    float s = 0.f;
    for (int k = lane; k < HH; k += 32) s = fmaf(xr[k], gr[k], s);
#pragma unroll
    for (int o = 16; o; o >>= 1) s += __shfl_xor_sync(0xffffffffu, s, o);
    if (lane == 0) logits[w] = s;
    __half* xo = g_xh + (size_t)t * HH;
    for (int k = tid; k < HH; k += 256) xo[k] = __float2half_rn(xr[k]);
    __syncthreads();
    if (tid == 0) {
        float m = logits[0];
#pragma unroll
        for (int i = 1; i < EE; ++i) m = fmaxf(m, logits[i]);
        float p[EE];
#pragma unroll
        for (int i = 0; i < EE; ++i) p[i] = expf(logits[i] - m);
        int a = 0;
#pragma unroll
        for (int i = 1; i < EE; ++i) if (p[i] > p[a]) a = i;
        int b = (a == 0) ? 1 : 0;
#pragma unroll
        for (int i = 0; i < EE; ++i) if (i != a && p[i] > p[b]) b = i;
        const float r = 1.f / (p[a] + p[b]);
        int pa = atomicAdd(&g_count[a], 1);
        g_tok[a * TT + pa] = t; g_wt[a * TT + pa] = p[a] * r;
        int pb = atomicAdd(&g_count[b], 1);
        g_tok[b * TT + pb] = t; g_wt[b * TT + pb] = p[b] * r;
    }
}

// ---------------------------------------------------------------------------
__device__ __forceinline__ uint32_t swz(uint32_t o) { return o ^ ((o >> 3) & 0x70); }

__device__ __forceinline__ void mma16(float* c, const uint32_t* a,
                                      uint32_t b0, uint32_t b1) {
    asm volatile(
        "mma.sync.aligned.m16n8k16.row.col.f32.f16.f16.f32 "
        "{%0,%1,%2,%3},{%4,%5,%6,%7},{%8,%9},{%0,%1,%2,%3};"
        : "+f"(c[0]), "+f"(c[1]), "+f"(c[2]), "+f"(c[3])
        : "r"(a[0]), "r"(a[1]), "r"(a[2]), "r"(a[3]), "r"(b0), "r"(b1));
}
#define LDM4(r, addr)                                                        \
    asm volatile("ldmatrix.sync.aligned.m8n8.x4.shared.b16 {%0,%1,%2,%3},[%4];" \
                 : "=r"((r)[0]), "=r"((r)[1]), "=r"((r)[2]), "=r"((r)[3])    \
                 : "r"(addr))
#define CP16(so, gp) \
    asm volatile("cp.async.cg.shared.global [%0], [%1], 16;" :: "r"(so), "l"(gp))
#define CP_COMMIT() asm volatile("cp.async.commit_group;" ::: "memory")
#define CP_WAIT1()  asm volatile("cp.async.wait_group 1;" ::: "memory")
#define CP_WAIT0()  asm volatile("cp.async.wait_group 0;" ::: "memory")

// ---------------------------------------------------------------------------
// GEMM1: block 128(M) x 64(N of gate AND up), BK=64 halves, 3-stage cp.async,
// all-fp16 smem with SW128 swizzle + ldmatrix. Warps 4(M) x 2(N);
// warp tile 32x32 dual accumulator (gate+up).   [identical to R8]
__global__ __launch_bounds__(256, 2) void gemm1_fp16() {
    extern __shared__ char smraw[];
    char* smal = (char*)(((uintptr_t)smraw + 1023) & ~(uintptr_t)1023);
    const int e = blockIdx.z;
    const int cnt = g_count[e];
    const int m0 = blockIdx.y * 128;
    if (m0 >= cnt) return;
    const int n0 = blockIdx.x * 64;

    const int tid = threadIdx.x;
    const uint32_t sbase = (uint32_t)__cvta_generic_to_shared(smal);

    const __half* aG[4]; uint32_t aS[4];
    const __half* bG[4]; uint32_t bS[4];
#pragma unroll
    for (int i = 0; i < 4; ++i) {
        int c = tid + i * 256;
        int r = c >> 3, kg = c & 7;
        int slot = m0 + r; if (slot > cnt - 1) slot = cnt - 1;
        aG[i] = g_xh + (size_t)g_tok[e * TT + slot] * HH + kg * 8;
        aS[i] = swz(r * 128 + kg * 16);
        size_t row = (r < 64) ? (size_t)(n0 + r) : (size_t)(II + n0 + (r - 64));
        bG[i] = g_w13h + (size_t)e * 2 * II * HH + row * HH + kg * 8;
        bS[i] = BOFF + swz(r * 128 + kg * 16);
    }

#define ISSUE1(s, k0)                                                   \
    {                                                                   \
        const uint32_t sb = sbase + (s) * STGB;                         \
        _Pragma("unroll") for (int i = 0; i < 4; ++i) {                 \
            CP16(sb + aS[i], aG[i] + (k0));                             \
            CP16(sb + bS[i], bG[i] + (k0));                             \
        }                                                               \
    }

    const int lane = tid & 31, wid = tid >> 5;
    const int grp = lane >> 2, tig = lane & 3;
    const int wm = (wid & 3) * 32, wn = (wid >> 2) * 32;

    const uint32_t arel = (uint32_t)(wm + (lane & 15)) * 128 + ((lane >> 4) & 1) * 16;
    const uint32_t amask = (arel >> 3) & 0x70;
    const uint32_t brel = (uint32_t)(wn + ((lane >> 4) & 1) * 8 + (lane & 7)) * 128
                        + ((lane >> 3) & 1) * 16;
    const uint32_t bmask = (brel >> 3) & 0x70;

    float cgr[2][4][4] = {};
    float cur[2][4][4] = {};

    ISSUE1(0, 0); CP_COMMIT();
    ISSUE1(1, 64); CP_COMMIT();

    const int NT = HH / 64;  // 32
    for (int k = 0; k < NT; ++k) {
        CP_WAIT1();
        __syncthreads();
        const uint32_t su = sbase + (k % 3) * STGB;
#pragma unroll
        for (int kc4 = 0; kc4 < 4; ++kc4) {
            const uint32_t kcb = kc4 * 32;
            uint32_t af[2][4];
#pragma unroll
            for (int i = 0; i < 2; ++i)
                LDM4(af[i], su + (((arel + kcb + 2048 * i) ^ amask)));
#pragma unroll
            for (int jj = 0; jj < 2; ++jj) {
                uint32_t bg[4], bu[4];
                const uint32_t bb = brel + kcb + 2048 * jj;
                LDM4(bg, su + BOFF + ((bb) ^ bmask));
                LDM4(bu, su + BOFF + ((bb + 8192) ^ bmask));
#pragma unroll
                for (int i = 0; i < 2; ++i) {
                    mma16(cgr[i][2 * jj],     af[i], bg[0], bg[1]);
                    mma16(cgr[i][2 * jj + 1], af[i], bg[2], bg[3]);
                    mma16(cur[i][2 * jj],     af[i], bu[0], bu[1]);
                    mma16(cur[i][2 * jj + 1], af[i], bu[2], bu[3]);
                }
            }
        }
        const int kn = k + 2;
        if (kn < NT) ISSUE1(kn % 3, kn * 64);
        CP_COMMIT();
    }
    CP_WAIT0();

    // epilogue: swiglu * wt -> g_hh (fp16)
#pragma unroll
    for (int i = 0; i < 2; ++i) {
#pragma unroll
        for (int half = 0; half < 2; ++half) {
            const int slot = m0 + wm + 16 * i + grp + 8 * half;
            if (slot < cnt) {
                const float wt = g_wt[e * TT + slot];
                __half* hrow = g_hh + ((size_t)e * TT + slot) * II + n0 + wn;
#pragma unroll
                for (int j = 0; j < 4; ++j) {
                    const float g0 = cgr[i][j][2 * half], g1 = cgr[i][j][2 * half + 1];
                    const float u0 = cur[i][j][2 * half], u1 = cur[i][j][2 * half + 1];
                    const float v0 = wt * (g0 / (1.f + __expf(-g0))) * u0;
                    const float v1 = wt * (g1 / (1.f + __expf(-g1))) * u1;
                    *(__half2*)&hrow[8 * j + 2 * tig] = __floats2half2_rn(v0, v1);
                }
            }
        }
    }
#undef ISSUE1
}

// ---------------------------------------------------------------------------
// GEMM2: block 128(M) x 128(N), BK=64 halves, 3-stage, all-fp16 + ldmatrix.
// Warps 4(M) x 2(N); warp tile 32x64. Scatter atomicAdd epilogue. [identical to R8]
__global__ __launch_bounds__(256, 2) void gemm2_fp16(float* __restrict__ out) {
    extern __shared__ char smraw[];
    char* smal = (char*)(((uintptr_t)smraw + 1023) & ~(uintptr_t)1023);
    const int e = blockIdx.z;
    const int cnt = g_count[e];
    const int m0 = blockIdx.y * 128;
    if (m0 >= cnt) return;
    const int n0 = blockIdx.x * 128;

    const int tid = threadIdx.x;
    const uint32_t sbase = (uint32_t)__cvta_generic_to_shared(smal);

    const __half* aG[4]; uint32_t aS[4];
    const __half* bG[4]; uint32_t bS[4];
#pragma unroll
    for (int i = 0; i < 4; ++i) {
        int c = tid + i * 256;
        int r = c >> 3, kg = c & 7;
        int slot = m0 + r; if (slot > cnt - 1) slot = cnt - 1;
        aG[i] = g_hh + ((size_t)e * TT + slot) * II + kg * 8;
        aS[i] = swz(r * 128 + kg * 16);
        bG[i] = g_w2h + (size_t)e * HH * II + (size_t)(n0 + r) * II + kg * 8;
        bS[i] = BOFF + swz(r * 128 + kg * 16);
    }

#define ISSUE2(s, k0)                                                   \
    {                                                                   \
        const uint32_t sb = sbase + (s) * STGB;                         \
        _Pragma("unroll") for (int i = 0; i < 4; ++i) {                 \
            CP16(sb + aS[i], aG[i] + (k0));                             \
            CP16(sb + bS[i], bG[i] + (k0));                             \
        }                                                               \
    }

    const int lane = tid & 31, wid = tid >> 5;
    const int grp = lane >> 2, tig = lane & 3;
    const int wm = (wid & 3) * 32, wn = (wid >> 2) * 64;

    const uint32_t arel = (uint32_t)(wm + (lane & 15)) * 128 + ((lane >> 4) & 1) * 16;
    const uint32_t amask = (arel >> 3) & 0x70;
    const uint32_t brel = (uint32_t)(wn + ((lane >> 4) & 1) * 8 + (lane & 7)) * 128
                        + ((lane >> 3) & 1) * 16;
    const uint32_t bmask = (brel >> 3) & 0x70;

    float cc[2][8][4] = {};

    ISSUE2(0, 0); CP_COMMIT();
    ISSUE2(1, 64); CP_COMMIT();

    const int NT = II / 64;  // 64
    for (int k = 0; k < NT; ++k) {
        CP_WAIT1();
        __syncthreads();
        const uint32_t su = sbase + (k % 3) * STGB;
#pragma unroll
        for (int kc4 = 0; kc4 < 4; ++kc4) {
            const uint32_t kcb = kc4 * 32;
            uint32_t af[2][4];
#pragma unroll
            for (int i = 0; i < 2; ++i)
                LDM4(af[i], su + (((arel + kcb + 2048 * i) ^ amask)));
#pragma unroll
            for (int jj = 0; jj < 4; ++jj) {
                uint32_t bb4[4];
                LDM4(bb4, su + BOFF + (((brel + kcb + 2048 * jj) ^ bmask)));
#pragma unroll
                for (int i = 0; i < 2; ++i) {
                    mma16(cc[i][2 * jj],     af[i], bb4[0], bb4[1]);
                    mma16(cc[i][2 * jj + 1], af[i], bb4[2], bb4[3]);
                }
            }
        }
        const int kn = k + 2;
        if (kn < NT) ISSUE2(kn % 3, kn * 64);
        CP_COMMIT();
    }
    CP_WAIT0();

#pragma unroll
    for (int i = 0; i < 2; ++i) {
#pragma unroll
        for (int half = 0; half < 2; ++half) {
            const int slot = m0 + wm + 16 * i + grp + 8 * half;
            if (slot < cnt) {
                const int tok = g_tok[e * TT + slot];
                float* orow = out + (size_t)tok * HH + n0 + wn;
#pragma unroll
                for (int j = 0; j < 8; ++j) {
                    atomicAdd(&orow[8 * j + 2 * tig], cc[i][j][2 * half]);
                    atomicAdd(&orow[8 * j + 2 * tig + 1], cc[i][j][2 * half + 1]);
                }
            }
        }
    }
#undef ISSUE2
}

// ---------------------------------------------------------------------------
extern "C" void kernel_launch(void* const* d_in, const int* in_sizes, int n_in,
                              void* d_out, int out_size) {
    const float* x   = (const float*)d_in[0];  // [T, H]
    const float* gw  = (const float*)d_in[1];  // [E, H]
    const float* w13 = (const float*)d_in[2];  // [E, 2I, H]
    const float* w2  = (const float*)d_in[3];  // [E, H, I]
    float* out = (float*)d_out;                // [T, H] fp32

    const int dsm = NSTAGE * STGB + 1024;  // 99328 B
    cudaFuncSetAttribute(gemm1_fp16, cudaFuncAttributeMaxDynamicSharedMemorySize, dsm);
    cudaFuncSetAttribute(gemm2_fp16, cudaFuncAttributeMaxDynamicSharedMemorySize, dsm);

    cudaMemsetAsync(out, 0, (size_t)TT * HH * sizeof(float));
    zero_counts_k<<<1, 32>>>();
    prep_k<<<CVTB + TT, 256>>>(x, gw, w13, w2);
    gemm1_fp16<<<dim3(II / 64, TT / 128, EE), 256, dsm>>>();
    gemm2_fp16<<<dim3(HH / 128, TT / 128, EE), 256, dsm>>>(out);
}